// round 2
// baseline (speedup 1.0000x reference)
#include <cuda_runtime.h>
#include <cstdint>

// Problem constants (fixed by the reference)
#define NUM_B     16
#define NUM_N     2048
#define NUM_Q     (NUM_B * NUM_N)   // 32768 queries
#define M_ANCH    8192
#define NPAIRS    (M_ANCH / 2)      // 4096 anchor pairs
#define BLOCK     128
#define CHUNK_PAIRS 512             // 1024 anchors per smem chunk (40 KB)
#define NCHUNK    (NPAIRS / CHUNK_PAIRS) // 8

// ---------- packed f32x2 helpers (sm_103a) ----------
__device__ __forceinline__ unsigned long long f2pk(float lo, float hi) {
    unsigned long long r;
    asm("mov.b64 %0, {%1, %2};" : "=l"(r) : "f"(lo), "f"(hi));
    return r;
}
__device__ __forceinline__ void f2upk(unsigned long long v, float& lo, float& hi) {
    asm("mov.b64 {%0, %1}, %2;" : "=f"(lo), "=f"(hi) : "l"(v));
}
__device__ __forceinline__ unsigned long long ffma2(unsigned long long a,
                                                    unsigned long long b,
                                                    unsigned long long c) {
    unsigned long long d;
    asm("fma.rn.f32x2 %0, %1, %2, %3;" : "=l"(d) : "l"(a), "l"(b), "l"(c));
    return d;
}

// smem layout per anchor pair (80 B, 16B-aligned rows):
//   [0..7]  : {a_even[k], a_odd[k]} packed f32x2 for k = 0..7
//   [8]     : {-0.5*||a_even||^2, -0.5*||a_odd||^2}
//   [9]     : pad
__global__ __launch_bounds__(BLOCK, 2)
void cold_diffusion_nn_kernel(const float* __restrict__ x_start,
                              const float* __restrict__ anchors,
                              const float* __restrict__ sqrt_ac,
                              const float* __restrict__ sqrt_om_ac,
                              const int*   __restrict__ t,
                              float*       __restrict__ out) {
    __shared__ __align__(16) unsigned long long sv[CHUNK_PAIRS][10];

    const int tid = threadIdx.x;
    const int q   = blockIdx.x * BLOCK + tid;   // query index, 0..32767

    // Load this thread's query vector (8 floats = 2x float4)
    const float4* x4 = reinterpret_cast<const float4*>(x_start);
    float4 xv0 = x4[2 * q];
    float4 xv1 = x4[2 * q + 1];

    // Duplicate-pack query dims: xx[k] = {x[k], x[k]}
    unsigned long long xx0 = f2pk(xv0.x, xv0.x);
    unsigned long long xx1 = f2pk(xv0.y, xv0.y);
    unsigned long long xx2 = f2pk(xv0.z, xv0.z);
    unsigned long long xx3 = f2pk(xv0.w, xv0.w);
    unsigned long long xx4 = f2pk(xv1.x, xv1.x);
    unsigned long long xx5 = f2pk(xv1.y, xv1.y);
    unsigned long long xx6 = f2pk(xv1.z, xv1.z);
    unsigned long long xx7 = f2pk(xv1.w, xv1.w);

    float best = -3.402823466e38f;  // maximize y = x.a - 0.5*||a||^2
    int   bi   = 0;

    const float4* a4 = reinterpret_cast<const float4*>(anchors);

    for (int c = 0; c < NCHUNK; c++) {
        const int pair_base = c * CHUNK_PAIRS;
        __syncthreads();
        // Cooperative fill: pack 2 anchors + norms per pair row
        for (int j = tid; j < CHUNK_PAIRS; j += BLOCK) {
            const int a0 = (pair_base + j) * 2;
            float4 p0 = a4[a0 * 2];
            float4 p1 = a4[a0 * 2 + 1];
            float4 q0 = a4[a0 * 2 + 2];
            float4 q1 = a4[a0 * 2 + 3];
            float n0 = p0.x * p0.x + p0.y * p0.y + p0.z * p0.z + p0.w * p0.w
                     + p1.x * p1.x + p1.y * p1.y + p1.z * p1.z + p1.w * p1.w;
            float n1 = q0.x * q0.x + q0.y * q0.y + q0.z * q0.z + q0.w * q0.w
                     + q1.x * q1.x + q1.y * q1.y + q1.z * q1.z + q1.w * q1.w;
            sv[j][0] = f2pk(p0.x, q0.x);
            sv[j][1] = f2pk(p0.y, q0.y);
            sv[j][2] = f2pk(p0.z, q0.z);
            sv[j][3] = f2pk(p0.w, q0.w);
            sv[j][4] = f2pk(p1.x, q1.x);
            sv[j][5] = f2pk(p1.y, q1.y);
            sv[j][6] = f2pk(p1.z, q1.z);
            sv[j][7] = f2pk(p1.w, q1.w);
            sv[j][8] = f2pk(-0.5f * n0, -0.5f * n1);
            sv[j][9] = 0ull;
        }
        __syncthreads();

        const int m_base = pair_base * 2;
        #pragma unroll 4
        for (int j = 0; j < CHUNK_PAIRS; j++) {
            const ulonglong2* row = reinterpret_cast<const ulonglong2*>(sv[j]);
            ulonglong2 v01 = row[0];
            ulonglong2 v23 = row[1];
            ulonglong2 v45 = row[2];
            ulonglong2 v67 = row[3];
            ulonglong2 nh  = row[4];  // .x = packed norms, .y = pad

            unsigned long long acc = nh.x;
            acc = ffma2(xx0, v01.x, acc);
            acc = ffma2(xx1, v01.y, acc);
            acc = ffma2(xx2, v23.x, acc);
            acc = ffma2(xx3, v23.y, acc);
            acc = ffma2(xx4, v45.x, acc);
            acc = ffma2(xx5, v45.y, acc);
            acc = ffma2(xx6, v67.x, acc);
            acc = ffma2(xx7, v67.y, acc);

            float s0, s1;
            f2upk(acc, s0, s1);
            // strict '>' keeps the earliest index on ties (matches argmin-first)
            if (s0 > best) { best = s0; bi = m_base + 2 * j; }
            if (s1 > best) { best = s1; bi = m_base + 2 * j + 1; }
        }
    }

    // Epilogue: out = sa*x + sb*anchors[bi]
    const int b  = q >> 11;           // q / 2048
    const int tt = t[b];
    const float sa = sqrt_ac[tt];
    const float sb = sqrt_om_ac[tt];

    float4 m0 = a4[2 * bi];
    float4 m1 = a4[2 * bi + 1];
    float4 o0, o1;
    o0.x = sa * xv0.x + sb * m0.x;
    o0.y = sa * xv0.y + sb * m0.y;
    o0.z = sa * xv0.z + sb * m0.z;
    o0.w = sa * xv0.w + sb * m0.w;
    o1.x = sa * xv1.x + sb * m1.x;
    o1.y = sa * xv1.y + sb * m1.y;
    o1.z = sa * xv1.z + sb * m1.z;
    o1.w = sa * xv1.w + sb * m1.w;

    float4* out4 = reinterpret_cast<float4*>(out);
    out4[2 * q]     = o0;
    out4[2 * q + 1] = o1;
}

extern "C" void kernel_launch(void* const* d_in, const int* in_sizes, int n_in,
                              void* d_out, int out_size) {
    const float* x_start   = (const float*)d_in[0];   // [16,2048,4,2]
    const float* anchors   = (const float*)d_in[1];   // [8192,4,2]
    const float* sqrt_ac   = (const float*)d_in[2];   // [1000]
    const float* sqrt_omac = (const float*)d_in[3];   // [1000]
    const int*   t         = (const int*)d_in[4];     // [16]
    float*       out       = (float*)d_out;           // [16,2048,4,2]

    (void)in_sizes; (void)n_in; (void)out_size;

    cold_diffusion_nn_kernel<<<NUM_Q / BLOCK, BLOCK>>>(
        x_start, anchors, sqrt_ac, sqrt_omac, t, out);
}